// round 11
// baseline (speedup 1.0000x reference)
#include <cuda_runtime.h>
#include <math.h>
#include <float.h>

// MMCL loss, B=1024 rows of N=32768, P=8 positives, H=327 hard negatives.
// Targets are int32 words (bool promoted). One CTA per row, two phases:
//   1) target-word scan (uint4, one zero-test per 16B) -> 8 positive values
//   2) branch-free logit scan (float4, predicated stores to per-thread slots)
// then purge one instance per positive value > T from the candidate multiset,
// exact 327th-largest via histogram + tie rank, double epilogue, fused
// last-CTA deterministic reduction.

#define Bn   1024
#define Nn   32768
#define Pp   8
#define Kk   327
#define NT   256
#define CAPT 16          // candidate slots per thread (mean 2.9 at T=2.0)
#define PSENT (-1e30f)

__device__ double g_partial[Bn];
__device__ int    g_done = 0;

__device__ __forceinline__ unsigned fkey(float f){
    unsigned u = __float_as_uint(f);
    return (u & 0x80000000u) ? ~u : (u | 0x80000000u);
}

__global__ __launch_bounds__(NT) void mmcl_kernel(
    const float* __restrict__ logits,
    const unsigned* __restrict__ tgw,
    float* __restrict__ out, int out_size)
{
    const int r = blockIdx.x, tid = threadIdx.x;
    const int lane = tid & 31, wid = tid >> 5;

    __shared__ float  s_vals[CAPT * NT];  // slot c of thread t at [c*NT + t]
    __shared__ int    s_hist[256];
    __shared__ float  s_tbuf[256];
    __shared__ double s_dred[NT];
    __shared__ float  s_pos[Pp];
    __shared__ float  s_red[NT/32];
    __shared__ int    s_ired[NT/32];
    __shared__ int    s_cnt_arr[NT];
    __shared__ int s_pcnt, s_ppos, s_tc, s_bstar, s_above, s_gt, s_ovf, s_claim, s_last;
    __shared__ unsigned s_maxkey;
    __shared__ float s_T, s_lob, s_hib, s_tau;

    const float* __restrict__ Lrow = logits + (size_t)r * Nn;
    const float4* __restrict__ L4 = (const float4*)Lrow;
    const uint4*  __restrict__ T4 = (const uint4*)(tgw + (size_t)r * Nn);

    if (tid == 0){ s_T = 2.0f; s_lob = -30.f; s_hib = 30.f; s_maxkey = 0u; s_pcnt = 0; }
    if (tid < Pp) s_pos[tid] = PSENT;
    __syncthreads();

    // ---- Phase 1: target scan (positives are 8/32768 -> rare path) ----
    #pragma unroll 8
    for (int j = tid; j < Nn/4; j += NT){
        uint4 t = T4[j];
        if (t.x | t.y | t.z | t.w){
            unsigned tt[4]; tt[0]=t.x; tt[1]=t.y; tt[2]=t.z; tt[3]=t.w;
            #pragma unroll
            for (int e = 0; e < 4; ++e){
                if (tt[e]){
                    int sl = atomicAdd(&s_pcnt, 1);
                    if (sl < Pp) s_pos[sl] = Lrow[4*j + e];
                }
            }
        }
    }
    __syncthreads();
    const int pcnt = min(s_pcnt, Pp);

    // ---- Phase 2: branch-free logit scan with bisection retry ----
    int myc = 0;
    float Tl = 2.0f;
    for (int attempt = 0; attempt < 64; ++attempt){
        __syncthreads();
        if (tid == 0){
            s_ovf = 0;
            int pp = 0;
            #pragma unroll
            for (int i = 0; i < Pp; ++i) pp += (s_pos[i] > s_T);
            s_ppos = pp;
        }
        __syncthreads();
        Tl = s_T;
        myc = 0;
        #pragma unroll 8
        for (int j = tid; j < Nn/4; j += NT){
            float4 v = L4[j];
            { bool c = (v.x > Tl); if (c){ if (myc < CAPT) s_vals[myc*NT+tid] = v.x; ++myc; } }
            { bool c = (v.y > Tl); if (c){ if (myc < CAPT) s_vals[myc*NT+tid] = v.y; ++myc; } }
            { bool c = (v.z > Tl); if (c){ if (myc < CAPT) s_vals[myc*NT+tid] = v.z; ++myc; } }
            { bool c = (v.w > Tl); if (c){ if (myc < CAPT) s_vals[myc*NT+tid] = v.w; ++myc; } }
        }
        if (myc > CAPT){ s_ovf = 1; myc = CAPT; }
        int t2 = myc;
        #pragma unroll
        for (int o = 16; o; o >>= 1) t2 += __shfl_xor_sync(0xffffffffu, t2, o);
        if (lane == 0) s_ired[wid] = t2;
        __syncthreads();
        int total = 0;
        #pragma unroll
        for (int w = 0; w < NT/32; ++w) total += s_ired[w];
        if (!s_ovf && (total - s_ppos) >= Kk) break;
        __syncthreads();
        if (tid == 0){
            if (s_ovf) s_lob = s_T;     // too many -> raise T
            else       s_hib = s_T;     // too few  -> lower T
            s_T = 0.5f * (s_lob + s_hib);
        }
    }

    // ---- purge exactly one candidate instance per positive value > Tl ----
    for (int q = 0; q < pcnt; ++q){
        __syncthreads();
        if (tid == 0) s_claim = -1;
        __syncthreads();
        float pv = s_pos[q];
        if (pv > Tl){
            int found = -1;
            for (int c = 0; c < myc; ++c){
                if (s_vals[c*NT + tid] == pv){ found = c; break; }
            }
            if (found >= 0) atomicCAS(&s_claim, -1, (tid << 8) | found);
        }
        __syncthreads();
        if (s_claim >= 0 && (s_claim >> 8) == tid){
            int c = s_claim & 0xff;
            --myc;
            s_vals[c*NT + tid] = s_vals[myc*NT + tid];
        }
    }
    __syncthreads();
    s_cnt_arr[tid] = myc;

    // ---- row max = max(purged candidates, positives) ----
    float lmax = -FLT_MAX;
    for (int c = 0; c < myc; ++c) lmax = fmaxf(lmax, s_vals[c*NT + tid]);
    if (tid < Pp){ float pv = s_pos[tid]; if (pv > -1e29f) lmax = fmaxf(lmax, pv); }
    unsigned mk = fkey(lmax);
    #pragma unroll
    for (int o = 16; o; o >>= 1) mk = max(mk, __shfl_xor_sync(0xffffffffu, mk, o));
    if (lane == 0) atomicMax(&s_maxkey, mk);
    __syncthreads();
    unsigned gk = s_maxkey;
    const float M = (gk & 0x80000000u) ? __uint_as_float(gk ^ 0x80000000u)
                                       : __uint_as_float(~gk);

    // ---- histogram over candidates to locate the Kk-th largest ----
    for (int b = tid; b < 256; b += NT) s_hist[b] = 0;
    if (tid == 0){ s_tau = Tl; s_gt = 0; }
    __syncthreads();
    const float scale = 256.0f / (M - Tl);
    for (int c = 0; c < myc; ++c){
        float v = s_vals[c*NT + tid];
        int b = (int)((v - Tl) * scale);
        b = min(max(b, 0), 255);
        atomicAdd(&s_hist[b], 1);
    }
    __syncthreads();
    if (tid == 0){
        int cum = 0, bs = 0;
        for (int b = 255; b >= 0; --b){
            int h = s_hist[b];
            if (cum + h >= Kk){ bs = b; break; }
            cum += h;
        }
        s_bstar = bs; s_above = cum; s_tc = 0;
    }
    __syncthreads();
    const int bstar = s_bstar, above = s_above;
    const int need  = Kk - above;

    // ---- exact tau (Kk-th largest) with tie count ----
    if (s_hist[bstar] <= 256){
        for (int c = 0; c < myc; ++c){
            float v = s_vals[c*NT + tid];
            int b = (int)((v - Tl) * scale); b = min(max(b, 0), 255);
            if (b == bstar){ int p = atomicAdd(&s_tc, 1); s_tbuf[p] = v; }
        }
        __syncthreads();
        int tc = s_tc;
        if (tid < tc){
            float v = s_tbuf[tid]; int gt = 0, eq = 0;
            for (int k2 = 0; k2 < tc; ++k2){
                float w = s_tbuf[k2];
                gt += (w > v); eq += (w == v);
            }
            if (gt < need && need <= gt + eq){ s_tau = v; s_gt = above + gt; }
        }
    } else {
        __syncthreads();
        for (int c = 0; c < myc; ++c){
            float v = s_vals[c*NT + tid];
            int gt = 0, eq = 0;
            for (int t3 = 0; t3 < NT; ++t3){
                int mc = s_cnt_arr[t3];
                for (int c2 = 0; c2 < mc; ++c2){
                    float w = s_vals[c2*NT + t3];
                    gt += (w > v); eq += (w == v);
                }
            }
            if (gt < Kk && Kk <= gt + eq){ s_tau = v; s_gt = gt; }
        }
    }
    __syncthreads();
    const float tau = s_tau;
    const int   gtc = s_gt;

    // ---- S = sum over top-Kk negatives of exp(10*(v - M)) ----
    float acc = 0.f;
    for (int c = 0; c < myc; ++c){
        float v = s_vals[c*NT + tid];
        if (v > tau) acc += expf(10.f * (v - M));
    }
    #pragma unroll
    for (int o = 16; o; o >>= 1) acc += __shfl_xor_sync(0xffffffffu, acc, o);
    if (lane == 0) s_red[wid] = acc;
    __syncthreads();

    // ---- per-row closed-form loss (double) ----
    if (tid == 0){
        double Md = (double)M;
        double S = (double)(Kk - gtc) * exp(10.0 * ((double)tau - Md));
        #pragma unroll
        for (int w = 0; w < NT/32; ++w) S += (double)s_red[w];

        double p[Pp];
        #pragma unroll
        for (int i = 0; i < Pp; ++i) p[i] = (double)s_pos[i];
        for (int i = 1; i < Pp; ++i){
            double x = p[i]; int j = i - 1;
            while (j >= 0 && p[j] < x){ p[j+1] = p[j]; --j; }
            p[j+1] = x;
        }
        double e[Pp], suf[Pp+1]; suf[Pp] = 0.0;
        for (int i = Pp-1; i >= 0; --i){
            e[i] = exp(10.0 * (p[i] - Md));
            suf[i] = suf[i+1] + e[i];
        }
        double lsum = 0.0;
        for (int i = 0; i < Pp; ++i){
            double inner = (double)(Pp - i) * e[i] + suf[Pp - i] + S;
            lsum += log(inner) + 10.0 * (Md - p[i]);
        }
        g_partial[r] = lsum;
        __threadfence();
        int old = atomicAdd(&g_done, 1);
        s_last = (old == Bn - 1) ? 1 : 0;
    }
    __syncthreads();

    // ---- last CTA: deterministic tree-reduce of the 1024 partials ----
    if (s_last){
        double a = g_partial[tid] + g_partial[tid + 256]
                 + g_partial[tid + 512] + g_partial[tid + 768];
        s_dred[tid] = a;
        __syncthreads();
        for (int s = 128; s > 0; s >>= 1){
            if (tid < s) s_dred[tid] += s_dred[tid + s];
            __syncthreads();
        }
        if (tid == 0){
            float val = (float)(s_dred[0] / (double)(Bn * Pp));
            for (int i = 0; i < out_size; ++i) out[i] = val;
            g_done = 0;   // reset for next graph replay
        }
    }
}

extern "C" void kernel_launch(void* const* d_in, const int* in_sizes, int n_in,
                              void* d_out, int out_size)
{
    const float* logits = (const float*)d_in[0];
    const unsigned* targets = (const unsigned*)d_in[1];
    mmcl_kernel<<<Bn, NT>>>(logits, targets, (float*)d_out, out_size);
}

// round 13
// speedup vs baseline: 1.0533x; 1.0533x over previous
#include <cuda_runtime.h>
#include <math.h>
#include <float.h>

// MMCL loss, B=1024 rows of N=32768, P=8 positives, H=327 hard negatives.
// Targets are int32 words (bool promoted). One CTA per row, two phases:
//   1) target-word scan: 8x uint4 batched loads (MLP=8), one zero-test/16B
//   2) logit scan: 8x float4 batched loads (MLP=8), predicated stores to
//      per-thread smem slots
// then purge one instance per positive value > T from the candidate multiset,
// exact 327th-largest via histogram + tie rank, double epilogue, fused
// last-CTA deterministic reduction.

#define Bn   1024
#define Nn   32768
#define Pp   8
#define Kk   327
#define NT   256
#define CAPT 16          // candidate slots per thread (mean 2.9 at T=2.0)
#define PSENT (-1e30f)

__device__ double g_partial[Bn];
__device__ int    g_done = 0;

__device__ __forceinline__ unsigned fkey(float f){
    unsigned u = __float_as_uint(f);
    return (u & 0x80000000u) ? ~u : (u | 0x80000000u);
}

__global__ __launch_bounds__(NT, 4) void mmcl_kernel(
    const float* __restrict__ logits,
    const unsigned* __restrict__ tgw,
    float* __restrict__ out, int out_size)
{
    const int r = blockIdx.x, tid = threadIdx.x;
    const int lane = tid & 31, wid = tid >> 5;

    __shared__ float  s_vals[CAPT * NT];  // slot c of thread t at [c*NT + t]
    __shared__ int    s_hist[256];
    __shared__ float  s_tbuf[256];
    __shared__ double s_dred[NT];
    __shared__ float  s_pos[Pp];
    __shared__ float  s_red[NT/32];
    __shared__ int    s_ired[NT/32];
    __shared__ int    s_cnt_arr[NT];
    __shared__ int s_pcnt, s_ppos, s_tc, s_bstar, s_above, s_gt, s_ovf, s_claim, s_last;
    __shared__ unsigned s_maxkey;
    __shared__ float s_T, s_lob, s_hib, s_tau;

    const float* __restrict__ Lrow = logits + (size_t)r * Nn;
    const float4* __restrict__ L4 = (const float4*)Lrow;
    const uint4*  __restrict__ T4 = (const uint4*)(tgw + (size_t)r * Nn);

    if (tid == 0){ s_T = 2.0f; s_lob = -30.f; s_hib = 30.f; s_maxkey = 0u; s_pcnt = 0; }
    if (tid < Pp) s_pos[tid] = PSENT;
    __syncthreads();

    // ---- Phase 1: target scan, 8-wide batched loads (positives rare) ----
    #pragma unroll
    for (int k = 0; k < 32; k += 8){
        uint4 t[8];
        #pragma unroll
        for (int u = 0; u < 8; ++u) t[u] = T4[(k+u)*NT + tid];
        #pragma unroll
        for (int u = 0; u < 8; ++u){
            if (t[u].x | t[u].y | t[u].z | t[u].w){
                int j = (k+u)*NT + tid;
                unsigned tt[4]; tt[0]=t[u].x; tt[1]=t[u].y; tt[2]=t[u].z; tt[3]=t[u].w;
                #pragma unroll
                for (int e = 0; e < 4; ++e){
                    if (tt[e]){
                        int sl = atomicAdd(&s_pcnt, 1);
                        if (sl < Pp) s_pos[sl] = Lrow[4*j + e];
                    }
                }
            }
        }
    }
    __syncthreads();
    const int pcnt = min(s_pcnt, Pp);

    // ---- Phase 2: logit scan, 8-wide batched loads, bisection retry ----
    int myc = 0;
    float Tl = 2.0f;
    for (int attempt = 0; attempt < 64; ++attempt){
        __syncthreads();
        if (tid == 0){
            s_ovf = 0;
            int pp = 0;
            #pragma unroll
            for (int i = 0; i < Pp; ++i) pp += (s_pos[i] > s_T);
            s_ppos = pp;
        }
        __syncthreads();
        Tl = s_T;
        myc = 0;
        #pragma unroll
        for (int k = 0; k < 32; k += 8){
            float4 v[8];
            #pragma unroll
            for (int u = 0; u < 8; ++u) v[u] = L4[(k+u)*NT + tid];
            #pragma unroll
            for (int u = 0; u < 8; ++u){
                { bool c = (v[u].x > Tl); if (c){ if (myc < CAPT) s_vals[myc*NT+tid] = v[u].x; ++myc; } }
                { bool c = (v[u].y > Tl); if (c){ if (myc < CAPT) s_vals[myc*NT+tid] = v[u].y; ++myc; } }
                { bool c = (v[u].z > Tl); if (c){ if (myc < CAPT) s_vals[myc*NT+tid] = v[u].z; ++myc; } }
                { bool c = (v[u].w > Tl); if (c){ if (myc < CAPT) s_vals[myc*NT+tid] = v[u].w; ++myc; } }
            }
        }
        if (myc > CAPT){ s_ovf = 1; myc = CAPT; }
        int t2 = myc;
        #pragma unroll
        for (int o = 16; o; o >>= 1) t2 += __shfl_xor_sync(0xffffffffu, t2, o);
        if (lane == 0) s_ired[wid] = t2;
        __syncthreads();
        int total = 0;
        #pragma unroll
        for (int w = 0; w < NT/32; ++w) total += s_ired[w];
        if (!s_ovf && (total - s_ppos) >= Kk) break;
        __syncthreads();
        if (tid == 0){
            if (s_ovf) s_lob = s_T;     // too many -> raise T
            else       s_hib = s_T;     // too few  -> lower T
            s_T = 0.5f * (s_lob + s_hib);
        }
    }

    // ---- purge exactly one candidate instance per positive value > Tl ----
    for (int q = 0; q < pcnt; ++q){
        __syncthreads();
        if (tid == 0) s_claim = -1;
        __syncthreads();
        float pv = s_pos[q];
        if (pv > Tl){
            int found = -1;
            for (int c = 0; c < myc; ++c){
                if (s_vals[c*NT + tid] == pv){ found = c; break; }
            }
            if (found >= 0) atomicCAS(&s_claim, -1, (tid << 8) | found);
        }
        __syncthreads();
        if (s_claim >= 0 && (s_claim >> 8) == tid){
            int c = s_claim & 0xff;
            --myc;
            s_vals[c*NT + tid] = s_vals[myc*NT + tid];
        }
    }
    __syncthreads();
    s_cnt_arr[tid] = myc;

    // ---- row max = max(purged candidates, positives) ----
    float lmax = -FLT_MAX;
    for (int c = 0; c < myc; ++c) lmax = fmaxf(lmax, s_vals[c*NT + tid]);
    if (tid < Pp){ float pv = s_pos[tid]; if (pv > -1e29f) lmax = fmaxf(lmax, pv); }
    unsigned mk = fkey(lmax);
    #pragma unroll
    for (int o = 16; o; o >>= 1) mk = max(mk, __shfl_xor_sync(0xffffffffu, mk, o));
    if (lane == 0) atomicMax(&s_maxkey, mk);
    __syncthreads();
    unsigned gk = s_maxkey;
    const float M = (gk & 0x80000000u) ? __uint_as_float(gk ^ 0x80000000u)
                                       : __uint_as_float(~gk);

    // ---- histogram over candidates to locate the Kk-th largest ----
    for (int b = tid; b < 256; b += NT) s_hist[b] = 0;
    if (tid == 0){ s_tau = Tl; s_gt = 0; }
    __syncthreads();
    const float scale = 256.0f / (M - Tl);
    for (int c = 0; c < myc; ++c){
        float v = s_vals[c*NT + tid];
        int b = (int)((v - Tl) * scale);
        b = min(max(b, 0), 255);
        atomicAdd(&s_hist[b], 1);
    }
    __syncthreads();
    if (tid == 0){
        int cum = 0, bs = 0;
        for (int b = 255; b >= 0; --b){
            int h = s_hist[b];
            if (cum + h >= Kk){ bs = b; break; }
            cum += h;
        }
        s_bstar = bs; s_above = cum; s_tc = 0;
    }
    __syncthreads();
    const int bstar = s_bstar, above = s_above;
    const int need  = Kk - above;

    // ---- exact tau (Kk-th largest) with tie count ----
    if (s_hist[bstar] <= 256){
        for (int c = 0; c < myc; ++c){
            float v = s_vals[c*NT + tid];
            int b = (int)((v - Tl) * scale); b = min(max(b, 0), 255);
            if (b == bstar){ int p = atomicAdd(&s_tc, 1); s_tbuf[p] = v; }
        }
        __syncthreads();
        int tc = s_tc;
        if (tid < tc){
            float v = s_tbuf[tid]; int gt = 0, eq = 0;
            for (int k2 = 0; k2 < tc; ++k2){
                float w = s_tbuf[k2];
                gt += (w > v); eq += (w == v);
            }
            if (gt < need && need <= gt + eq){ s_tau = v; s_gt = above + gt; }
        }
    } else {
        __syncthreads();
        for (int c = 0; c < myc; ++c){
            float v = s_vals[c*NT + tid];
            int gt = 0, eq = 0;
            for (int t3 = 0; t3 < NT; ++t3){
                int mc = s_cnt_arr[t3];
                for (int c2 = 0; c2 < mc; ++c2){
                    float w = s_vals[c2*NT + t3];
                    gt += (w > v); eq += (w == v);
                }
            }
            if (gt < Kk && Kk <= gt + eq){ s_tau = v; s_gt = gt; }
        }
    }
    __syncthreads();
    const float tau = s_tau;
    const int   gtc = s_gt;

    // ---- S = sum over top-Kk negatives of exp(10*(v - M)) ----
    float acc = 0.f;
    for (int c = 0; c < myc; ++c){
        float v = s_vals[c*NT + tid];
        if (v > tau) acc += expf(10.f * (v - M));
    }
    #pragma unroll
    for (int o = 16; o; o >>= 1) acc += __shfl_xor_sync(0xffffffffu, acc, o);
    if (lane == 0) s_red[wid] = acc;
    __syncthreads();

    // ---- per-row closed-form loss (double) ----
    if (tid == 0){
        double Md = (double)M;
        double S = (double)(Kk - gtc) * exp(10.0 * ((double)tau - Md));
        #pragma unroll
        for (int w = 0; w < NT/32; ++w) S += (double)s_red[w];

        double p[Pp];
        #pragma unroll
        for (int i = 0; i < Pp; ++i) p[i] = (double)s_pos[i];
        for (int i = 1; i < Pp; ++i){
            double x = p[i]; int j = i - 1;
            while (j >= 0 && p[j] < x){ p[j+1] = p[j]; --j; }
            p[j+1] = x;
        }
        double e[Pp], suf[Pp+1]; suf[Pp] = 0.0;
        for (int i = Pp-1; i >= 0; --i){
            e[i] = exp(10.0 * (p[i] - Md));
            suf[i] = suf[i+1] + e[i];
        }
        double lsum = 0.0;
        for (int i = 0; i < Pp; ++i){
            double inner = (double)(Pp - i) * e[i] + suf[Pp - i] + S;
            lsum += log(inner) + 10.0 * (Md - p[i]);
        }
        g_partial[r] = lsum;
        __threadfence();
        int old = atomicAdd(&g_done, 1);
        s_last = (old == Bn - 1) ? 1 : 0;
    }
    __syncthreads();

    // ---- last CTA: deterministic tree-reduce of the 1024 partials ----
    if (s_last){
        double a = g_partial[tid] + g_partial[tid + 256]
                 + g_partial[tid + 512] + g_partial[tid + 768];
        s_dred[tid] = a;
        __syncthreads();
        for (int s = 128; s > 0; s >>= 1){
            if (tid < s) s_dred[tid] += s_dred[tid + s];
            __syncthreads();
        }
        if (tid == 0){
            float val = (float)(s_dred[0] / (double)(Bn * Pp));
            for (int i = 0; i < out_size; ++i) out[i] = val;
            g_done = 0;   // reset for next graph replay
        }
    }
}

extern "C" void kernel_launch(void* const* d_in, const int* in_sizes, int n_in,
                              void* d_out, int out_size)
{
    const float* logits = (const float*)d_in[0];
    const unsigned* targets = (const unsigned*)d_in[1];
    mmcl_kernel<<<Bn, NT>>>(logits, targets, (float*)d_out, out_size);
}